// round 1
// baseline (speedup 1.0000x reference)
#include <cuda_runtime.h>
#include <math.h>
#include <stdint.h>

#define DIMV   1024
#define NHEADS 16
#define DK     64
#define RFF    128
#define FEAT   256      // 2*RFF
#define BATCH  2
#define SEQ    8192
#define MROWS  (BATCH*SEQ)       // 16384
#define NCHUNK 16                // kv chunks along sequence
#define INV_SQRT_R 0.08838834764831845f  // 1/sqrt(128)

// ---------------- scratch (device globals: no allocation allowed) ----------------
__device__ float g_q[MROWS * DIMV];       // 64 MB
__device__ float g_k[MROWS * DIMV];       // 64 MB
__device__ float g_v[MROWS * DIMV];       // 64 MB
__device__ float g_attn[MROWS * DIMV];    // 64 MB
__device__ float g_kv[BATCH * NHEADS * FEAT * DK];          // 512K floats
__device__ float g_ksum[BATCH * NHEADS * FEAT];             // 8K floats
__device__ float g_kv_part[NCHUNK * BATCH * NHEADS * FEAT * DK];   // 8.4M floats
__device__ float g_ksum_part[NCHUNK * BATCH * NHEADS * FEAT];      // 131K floats

// ---------------- SGEMM: C[M,Nn] = A[M,K] @ B[Nn,K]^T (+bias) ----------------
// 128x128 block tile, BK=16, 256 threads, 8x8 microtile split as 4+4 (conflict-free LDS.128)
__global__ __launch_bounds__(256) void sgemm_nt(
    const float* __restrict__ A, const float* __restrict__ Bw,
    const float* __restrict__ bias, float* __restrict__ C,
    int M, int Nn, int K)
{
    __shared__ float As[16][132];
    __shared__ float Bs[16][132];

    const int tid = threadIdx.x;
    const int tx = tid & 15;        // n direction
    const int ty = tid >> 4;        // m direction
    const int m0 = blockIdx.y * 128;
    const int n0 = blockIdx.x * 128;

    float acc[8][8];
    #pragma unroll
    for (int i = 0; i < 8; i++)
        #pragma unroll
        for (int j = 0; j < 8; j++) acc[i][j] = 0.f;

    for (int kt = 0; kt < K; kt += 16) {
        #pragma unroll
        for (int s = 0; s < 2; s++) {
            int idx = tid + 256 * s;          // 0..511
            int row = idx >> 2;               // 0..127
            int kc  = (idx & 3) << 2;         // 0,4,8,12
            float4 a4 = *(const float4*)&A[(size_t)(m0 + row) * K + kt + kc];
            As[kc + 0][row] = a4.x; As[kc + 1][row] = a4.y;
            As[kc + 2][row] = a4.z; As[kc + 3][row] = a4.w;
            float4 b4 = *(const float4*)&Bw[(size_t)(n0 + row) * K + kt + kc];
            Bs[kc + 0][row] = b4.x; Bs[kc + 1][row] = b4.y;
            Bs[kc + 2][row] = b4.z; Bs[kc + 3][row] = b4.w;
        }
        __syncthreads();
        #pragma unroll
        for (int k = 0; k < 16; k++) {
            float a[8], b[8];
            *(float4*)&a[0] = *(float4*)&As[k][ty * 4];
            *(float4*)&a[4] = *(float4*)&As[k][64 + ty * 4];
            *(float4*)&b[0] = *(float4*)&Bs[k][tx * 4];
            *(float4*)&b[4] = *(float4*)&Bs[k][64 + tx * 4];
            #pragma unroll
            for (int i = 0; i < 8; i++)
                #pragma unroll
                for (int j = 0; j < 8; j++)
                    acc[i][j] += a[i] * b[j];
        }
        __syncthreads();
    }

    float bv[8];
    #pragma unroll
    for (int j = 0; j < 8; j++) {
        int n = n0 + ((j < 4) ? (tx * 4 + j) : (64 + tx * 4 + j - 4));
        bv[j] = bias ? bias[n] : 0.f;
    }
    #pragma unroll
    for (int i = 0; i < 8; i++) {
        int m = m0 + ((i < 4) ? (ty * 4 + i) : (64 + ty * 4 + i - 4));
        float4 o0 = {acc[i][0] + bv[0], acc[i][1] + bv[1], acc[i][2] + bv[2], acc[i][3] + bv[3]};
        float4 o1 = {acc[i][4] + bv[4], acc[i][5] + bv[5], acc[i][6] + bv[6], acc[i][7] + bv[7]};
        *(float4*)&C[(size_t)m * Nn + n0 + tx * 4]      = o0;
        *(float4*)&C[(size_t)m * Nn + n0 + 64 + tx * 4] = o1;
    }
}

// ---------------- KV accumulation: partial Kv[f,d] and ksum[f] per (chunk, b, h) ----------------
// grid: (NCHUNK, B*H), 256 threads. Deterministic (no atomics): each block writes its own partial.
__global__ __launch_bounds__(256) void kv_accum(
    const float* __restrict__ kmat, const float* __restrict__ vmat,
    const float* __restrict__ Wr, const float* __restrict__ br)
{
    extern __shared__ float sm[];
    float* Wr_s = sm;                 // 64*128 = 8192
    float* br_s = Wr_s + 8192;        // 128
    float* k_s  = br_s + 128;         // 16*64
    float* v_s  = k_s + 1024;         // 16*64
    float* kf_s = v_s + 1024;         // 16*256

    const int tid = threadIdx.x;
    const int bh  = blockIdx.y;            // 0..31
    const int b   = bh >> 4, h = bh & 15;
    const int chunk = SEQ / NCHUNK;        // 512
    const int n0 = blockIdx.x * chunk;

    const float* WrH = Wr + (size_t)h * DK * RFF;
    for (int i = tid; i < 2048; i += 256)
        *(float4*)&Wr_s[i * 4] = *(const float4*)&WrH[i * 4];
    if (tid < 128) br_s[tid] = br[h * RFF + tid];

    const int f_grp = tid >> 3;       // 0..31 (8 f-values each)
    const int d_grp = tid & 7;        // 0..7  (8 d-values each)
    const int pn = tid >> 4;          // 0..15 (row within slab, proj phase)
    const int rb = (tid & 15) << 3;   // 0..120 (8 r-values, proj phase)

    float acc[8][8];
    #pragma unroll
    for (int i = 0; i < 8; i++)
        #pragma unroll
        for (int j = 0; j < 8; j++) acc[i][j] = 0.f;
    float ksacc[8] = {0, 0, 0, 0, 0, 0, 0, 0};

    const float* kbase = kmat + (size_t)(b * SEQ + n0) * DIMV + h * DK;
    const float* vbase = vmat + (size_t)(b * SEQ + n0) * DIMV + h * DK;

    __syncthreads();

    for (int nn = 0; nn < chunk; nn += 16) {
        {
            int row = tid >> 4, c = (tid & 15) << 2;
            *(float4*)&k_s[row * 64 + c] = *(const float4*)&kbase[(size_t)(nn + row) * DIMV + c];
            *(float4*)&v_s[row * 64 + c] = *(const float4*)&vbase[(size_t)(nn + row) * DIMV + c];
        }
        __syncthreads();
        {   // proj + phi for 16 rows x 128 r
            float p[8];
            #pragma unroll
            for (int j = 0; j < 8; j++) p[j] = br_s[rb + j];
            #pragma unroll 8
            for (int d = 0; d < 64; d++) {
                float kv = k_s[pn * 64 + d];
                float4 w0 = *(float4*)&Wr_s[d * 128 + rb];
                float4 w1 = *(float4*)&Wr_s[d * 128 + rb + 4];
                p[0] += kv * w0.x; p[1] += kv * w0.y; p[2] += kv * w0.z; p[3] += kv * w0.w;
                p[4] += kv * w1.x; p[5] += kv * w1.y; p[6] += kv * w1.z; p[7] += kv * w1.w;
            }
            #pragma unroll
            for (int j = 0; j < 8; j++) {
                float sv, cv;
                __sincosf(p[j], &sv, &cv);
                kf_s[pn * 256 + rb + j]       = cv * INV_SQRT_R;
                kf_s[pn * 256 + 128 + rb + j] = sv * INV_SQRT_R;
            }
        }
        __syncthreads();
        #pragma unroll
        for (int kk = 0; kk < 16; kk++) {
            float a[8], bb[8];
            *(float4*)&a[0] = *(float4*)&kf_s[kk * 256 + f_grp * 8];
            *(float4*)&a[4] = *(float4*)&kf_s[kk * 256 + f_grp * 8 + 4];
            *(float4*)&bb[0] = *(float4*)&v_s[kk * 64 + d_grp * 8];
            *(float4*)&bb[4] = *(float4*)&v_s[kk * 64 + d_grp * 8 + 4];
            #pragma unroll
            for (int i = 0; i < 8; i++)
                #pragma unroll
                for (int j = 0; j < 8; j++)
                    acc[i][j] += a[i] * bb[j];
            if (d_grp == 0) {
                #pragma unroll
                for (int i = 0; i < 8; i++) ksacc[i] += a[i];
            }
        }
        __syncthreads();
    }

    float* dst = g_kv_part + ((size_t)blockIdx.x * 32 + bh) * FEAT * DK;
    #pragma unroll
    for (int i = 0; i < 8; i++)
        #pragma unroll
        for (int j = 0; j < 8; j++)
            dst[(f_grp * 8 + i) * DK + d_grp * 8 + j] = acc[i][j];
    if (d_grp == 0) {
        float* kd = g_ksum_part + ((size_t)blockIdx.x * 32 + bh) * FEAT;
        #pragma unroll
        for (int i = 0; i < 8; i++) kd[f_grp * 8 + i] = ksacc[i];
    }
}

// ---------------- deterministic reduce of partials ----------------
__global__ __launch_bounds__(256) void kv_reduce()
{
    int i = blockIdx.x * 256 + threadIdx.x;
    if (i < BATCH * NHEADS * FEAT * DK) {
        int bh = i / (FEAT * DK);
        int e  = i % (FEAT * DK);
        float s = 0.f;
        #pragma unroll
        for (int c = 0; c < NCHUNK; c++)
            s += g_kv_part[((size_t)c * 32 + bh) * FEAT * DK + e];
        g_kv[i] = s;
    }
    if (i < BATCH * NHEADS * FEAT) {
        int bh = i / FEAT;
        int e  = i % FEAT;
        float s = 0.f;
        #pragma unroll
        for (int c = 0; c < NCHUNK; c++)
            s += g_ksum_part[((size_t)c * 32 + bh) * FEAT + e];
        g_ksum[i] = s;
    }
}

// ---------------- query side: out = (qf @ Kv) * z, fused RFF ----------------
// grid: (SEQ/128, B*H), 256 threads, 128 rows per block in 16-row slabs.
__global__ __launch_bounds__(256) void attn_out(
    const float* __restrict__ qmat,
    const float* __restrict__ Wr, const float* __restrict__ br)
{
    extern __shared__ float sm[];
    float* Wr_s   = sm;                  // 8192
    float* br_s   = Wr_s + 8192;         // 128
    float* ksum_s = br_s + 128;          // 256
    float* Kv_s   = ksum_s + 256;        // 16384
    float* q_s    = Kv_s + 16384;        // 1024
    float* qf_s   = q_s + 1024;          // 4096
    float* z_s    = qf_s + 4096;         // 16

    const int tid = threadIdx.x;
    const int bh  = blockIdx.y;
    const int b   = bh >> 4, h = bh & 15;
    const int rows0 = blockIdx.x * 128;

    const float* WrH = Wr + (size_t)h * DK * RFF;
    for (int i = tid; i < 2048; i += 256)
        *(float4*)&Wr_s[i * 4] = *(const float4*)&WrH[i * 4];
    if (tid < 128) br_s[tid] = br[h * RFF + tid];
    ksum_s[tid] = g_ksum[bh * FEAT + tid];
    {
        const float* KvB = g_kv + (size_t)bh * FEAT * DK;
        for (int i = tid; i < 4096; i += 256)
            *(float4*)&Kv_s[i * 4] = *(const float4*)&KvB[i * 4];
    }
    __syncthreads();

    const int pn = tid >> 4;
    const int rb = (tid & 15) << 3;

    const float* qbase = qmat + (size_t)(b * SEQ + rows0) * DIMV + h * DK;
    float* obase = g_attn + (size_t)(b * SEQ + rows0) * DIMV + h * DK;

    for (int ss = 0; ss < 128; ss += 16) {
        {
            int row = tid >> 4, c = (tid & 15) << 2;
            *(float4*)&q_s[row * 64 + c] = *(const float4*)&qbase[(size_t)(ss + row) * DIMV + c];
        }
        __syncthreads();
        {   // proj + phi
            float p[8];
            #pragma unroll
            for (int j = 0; j < 8; j++) p[j] = br_s[rb + j];
            #pragma unroll 8
            for (int d = 0; d < 64; d++) {
                float qv = q_s[pn * 64 + d];
                float4 w0 = *(float4*)&Wr_s[d * 128 + rb];
                float4 w1 = *(float4*)&Wr_s[d * 128 + rb + 4];
                p[0] += qv * w0.x; p[1] += qv * w0.y; p[2] += qv * w0.z; p[3] += qv * w0.w;
                p[4] += qv * w1.x; p[5] += qv * w1.y; p[6] += qv * w1.z; p[7] += qv * w1.w;
            }
            #pragma unroll
            for (int j = 0; j < 8; j++) {
                float sv, cv;
                __sincosf(p[j], &sv, &cv);
                qf_s[pn * 256 + rb + j]       = cv * INV_SQRT_R;
                qf_s[pn * 256 + 128 + rb + j] = sv * INV_SQRT_R;
            }
        }
        __syncthreads();
        if (tid < 16) {
            float acc = 0.f;
            #pragma unroll 8
            for (int f = 0; f < FEAT; f++) acc += qf_s[tid * 256 + f] * ksum_s[f];
            z_s[tid] = 1.f / (acc + 1e-6f);
        }
        __syncthreads();
        {
            int row = tid >> 4, db = (tid & 15) << 2;
            float4 o = {0.f, 0.f, 0.f, 0.f};
            #pragma unroll 8
            for (int f = 0; f < FEAT; f++) {
                float qv = qf_s[row * 256 + f];
                float4 kv = *(float4*)&Kv_s[f * 64 + db];
                o.x += qv * kv.x; o.y += qv * kv.y; o.z += qv * kv.z; o.w += qv * kv.w;
            }
            float zz = z_s[row];
            o.x *= zz; o.y *= zz; o.z *= zz; o.w *= zz;
            *(float4*)&obase[(size_t)(ss + row) * DIMV + db] = o;
        }
        __syncthreads();
    }
}

// ---------------- launch ----------------
extern "C" void kernel_launch(void* const* d_in, const int* in_sizes, int n_in,
                              void* d_out, int out_size)
{
    const float* x  = (const float*)d_in[0];
    const float* Wq = (const float*)d_in[1];
    const float* Wk = (const float*)d_in[2];
    const float* Wv = (const float*)d_in[3];
    const float* Wp = (const float*)d_in[4];
    const float* bp = (const float*)d_in[5];
    const float* Wr = (const float*)d_in[6];
    const float* br = (const float*)d_in[7];
    float* out = (float*)d_out;

    float *qp, *kp, *vp, *ap;
    cudaGetSymbolAddress((void**)&qp, g_q);
    cudaGetSymbolAddress((void**)&kp, g_k);
    cudaGetSymbolAddress((void**)&vp, g_v);
    cudaGetSymbolAddress((void**)&ap, g_attn);

    const int smem_kv   = 14464 * 4;   // 57856 B
    const int smem_attn = 30096 * 4;   // 120384 B
    cudaFuncSetAttribute(kv_accum, cudaFuncAttributeMaxDynamicSharedMemorySize, smem_kv);
    cudaFuncSetAttribute(attn_out, cudaFuncAttributeMaxDynamicSharedMemorySize, smem_attn);

    dim3 gg(DIMV / 128, MROWS / 128);   // 8 x 128
    sgemm_nt<<<gg, 256>>>(x, Wq, nullptr, qp, MROWS, DIMV, DIMV);
    sgemm_nt<<<gg, 256>>>(x, Wk, nullptr, kp, MROWS, DIMV, DIMV);
    sgemm_nt<<<gg, 256>>>(x, Wv, nullptr, vp, MROWS, DIMV, DIMV);

    kv_accum<<<dim3(NCHUNK, BATCH * NHEADS), 256, smem_kv>>>(kp, vp, Wr, br);
    kv_reduce<<<(BATCH * NHEADS * FEAT * DK + 255) / 256, 256>>>();
    attn_out<<<dim3(SEQ / 128, BATCH * NHEADS), 256, smem_attn>>>(qp, Wr, br);

    sgemm_nt<<<gg, 256>>>(ap, Wp, bp, out, MROWS, DIMV, DIMV);
}

// round 3
// speedup vs baseline: 1.4578x; 1.4578x over previous
#include <cuda_runtime.h>
#include <cuda_bf16.h>
#include <math.h>
#include <stdint.h>

#define DIMV   1024
#define NHEADS 16
#define DK     64
#define RFF    128
#define FEAT   256
#define BATCH  2
#define SEQ    8192
#define MROWS  (BATCH*SEQ)       // 16384
#define NCHUNK 16
#define INV_SQRT_R 0.08838834764831845f

// ---------------- scratch (device globals) ----------------
__device__ float g_q[MROWS * DIMV];
__device__ float g_k[MROWS * DIMV];
__device__ float g_v[MROWS * DIMV];
__device__ float g_attn[MROWS * DIMV];
__device__ float g_kv[BATCH * NHEADS * FEAT * DK];
__device__ float g_ksum[BATCH * NHEADS * FEAT];
__device__ float g_kv_part[NCHUNK * BATCH * NHEADS * FEAT * DK];
__device__ float g_ksum_part[NCHUNK * BATCH * NHEADS * FEAT];

__device__ __nv_bfloat16 g_xh[MROWS * DIMV];
__device__ __nv_bfloat16 g_xl[MROWS * DIMV];
__device__ __nv_bfloat16 g_ah[MROWS * DIMV];
__device__ __nv_bfloat16 g_al[MROWS * DIMV];
__device__ __nv_bfloat16 g_wh[4 * DIMV * DIMV];
__device__ __nv_bfloat16 g_wl[4 * DIMV * DIMV];

// ---------------- PTX helpers (sm_80-era: compile under compute_100) ----------------
__device__ __forceinline__ uint32_t smem_u32(const void* p) {
    uint32_t a;
    asm("{ .reg .u64 t; cvta.to.shared.u64 t, %1; cvt.u32.u64 %0, t; }" : "=r"(a) : "l"(p));
    return a;
}
__device__ __forceinline__ void cpa16(uint32_t s, const void* g) {
    asm volatile("cp.async.cg.shared.global [%0], [%1], 16;" :: "r"(s), "l"(g));
}
__device__ __forceinline__ void cpa_commit() {
    asm volatile("cp.async.commit_group;");
}
__device__ __forceinline__ void ldmx4(uint32_t addr, uint32_t& r0, uint32_t& r1, uint32_t& r2, uint32_t& r3) {
    asm volatile("ldmatrix.sync.aligned.m8n8.x4.shared.b16 {%0,%1,%2,%3}, [%4];"
                 : "=r"(r0), "=r"(r1), "=r"(r2), "=r"(r3) : "r"(addr));
}
__device__ __forceinline__ void mma16816(float* d, const uint32_t* a, const uint32_t* b) {
    asm volatile(
        "mma.sync.aligned.m16n8k16.row.col.f32.bf16.bf16.f32 "
        "{%0,%1,%2,%3}, {%4,%5,%6,%7}, {%8,%9}, {%0,%1,%2,%3};"
        : "+f"(d[0]), "+f"(d[1]), "+f"(d[2]), "+f"(d[3])
        : "r"(a[0]), "r"(a[1]), "r"(a[2]), "r"(a[3]), "r"(b[0]), "r"(b[1]));
}

// ---------------- fp32 -> (hi, lo) bf16 split ----------------
__global__ __launch_bounds__(256) void split_bf16(
    const float* __restrict__ in, __nv_bfloat16* __restrict__ hi,
    __nv_bfloat16* __restrict__ lo, int n4)
{
    int i = blockIdx.x * 256 + threadIdx.x;
    if (i >= n4) return;
    float4 v = ((const float4*)in)[i];
    __nv_bfloat16 h0 = __float2bfloat16(v.x);
    __nv_bfloat16 h1 = __float2bfloat16(v.y);
    __nv_bfloat16 h2 = __float2bfloat16(v.z);
    __nv_bfloat16 h3 = __float2bfloat16(v.w);
    __nv_bfloat16 l0 = __float2bfloat16(v.x - __bfloat162float(h0));
    __nv_bfloat16 l1 = __float2bfloat16(v.y - __bfloat162float(h1));
    __nv_bfloat16 l2 = __float2bfloat16(v.z - __bfloat162float(h2));
    __nv_bfloat16 l3 = __float2bfloat16(v.w - __bfloat162float(h3));
    __nv_bfloat162* H = (__nv_bfloat162*)hi;
    __nv_bfloat162* L = (__nv_bfloat162*)lo;
    __nv_bfloat162 a; a.x = h0; a.y = h1;
    __nv_bfloat162 b; b.x = h2; b.y = h3;
    __nv_bfloat162 c; c.x = l0; c.y = l1;
    __nv_bfloat162 d; d.x = l2; d.y = l3;
    H[2*i] = a; H[2*i+1] = b;
    L[2*i] = c; L[2*i+1] = d;
}

// ---------------- bf16x3 GEMM via mma.sync: C[M,1024] = A @ B^T (+bias) ----------------
// 128x128 CTA tile, 8 warps (2x4, 64x32 warp tiles), BK=32, cp.async double buffer.
// SMEM stage: Ah[128x32] Al Bh Bl (8KB each, 32KB/stage, 64KB total).
// Swizzle: 16B quad q at row r stored at q ^ ((r>>1)&3).
#define GSTAGE 32768
#define GEMM_SMEM (2 * GSTAGE)

__global__ __launch_bounds__(256, 1) void gemm_bf16x3(
    const __nv_bfloat16* __restrict__ Ah, const __nv_bfloat16* __restrict__ Al,
    const __nv_bfloat16* __restrict__ Bh, const __nv_bfloat16* __restrict__ Bl,
    const float* __restrict__ bias, float* __restrict__ C)
{
    extern __shared__ __align__(128) char sm[];
    const int tid = threadIdx.x, wid = tid >> 5, lid = tid & 31;
    const int m0 = blockIdx.y * 128, n0 = blockIdx.x * 128;
    const int wm = (wid & 1) * 64;      // warp m offset in tile
    const int wn = (wid >> 1) * 32;     // warp n offset in tile
    const uint32_t smb = smem_u32(sm);

    float acc[4][4][4];
    #pragma unroll
    for (int i = 0; i < 4; i++)
        #pragma unroll
        for (int j = 0; j < 4; j++)
            #pragma unroll
            for (int e = 0; e < 4; e++) acc[i][j][e] = 0.f;

    // ---- stage loader ----
    auto load_stage = [&](int ci, int s) {
        const int k0 = ci * 32;
        const uint32_t sb = smb + s * GSTAGE;
        #pragma unroll
        for (int it = 0; it < 2; it++) {
            int t = tid + it * 256;            // 0..511
            int row = t >> 2, q = t & 3;
            uint32_t soff = row * 64 + ((q ^ ((row >> 1) & 3)) << 4);
            size_t ga = (size_t)(m0 + row) * DIMV + k0 + q * 8;
            size_t gb = (size_t)(n0 + row) * DIMV + k0 + q * 8;
            cpa16(sb + soff,         Ah + ga);
            cpa16(sb + 8192  + soff, Al + ga);
            cpa16(sb + 16384 + soff, Bh + gb);
            cpa16(sb + 24576 + soff, Bl + gb);
        }
        cpa_commit();
    };

    load_stage(0, 0);

    #pragma unroll 1
    for (int ci = 0; ci < 32; ci++) {
        const int s = ci & 1;
        if (ci < 31) load_stage(ci + 1, s ^ 1);
        if (ci < 31) asm volatile("cp.async.wait_group 1;");
        else         asm volatile("cp.async.wait_group 0;");
        __syncthreads();

        const uint32_t sb = smb + s * GSTAGE;
        #pragma unroll
        for (int ks = 0; ks < 2; ks++) {
            uint32_t aH[4][4], aL[4][4], bH[4][2], bL[4][2];
            // A fragments: 4 m-frags of 16 rows
            #pragma unroll
            for (int mi = 0; mi < 4; mi++) {
                int row = wm + mi * 16 + (lid & 7) + ((lid >> 3) & 1) * 8;
                int q = ks * 2 + (lid >> 4);
                uint32_t off = row * 64 + ((q ^ ((row >> 1) & 3)) << 4);
                ldmx4(sb + off,        aH[mi][0], aH[mi][1], aH[mi][2], aH[mi][3]);
                ldmx4(sb + 8192 + off, aL[mi][0], aL[mi][1], aL[mi][2], aL[mi][3]);
            }
            // B fragments: 4 n-frags of 8 rows, loaded in pairs
            #pragma unroll
            for (int np = 0; np < 2; np++) {
                int row = wn + np * 16 + (lid >> 4) * 8 + (lid & 7);
                int q = ks * 2 + ((lid >> 3) & 1);
                uint32_t off = row * 64 + ((q ^ ((row >> 1) & 3)) << 4);
                ldmx4(sb + 16384 + off, bH[2*np][0], bH[2*np][1], bH[2*np+1][0], bH[2*np+1][1]);
                ldmx4(sb + 24576 + off, bL[2*np][0], bL[2*np][1], bL[2*np+1][0], bL[2*np+1][1]);
            }
            #pragma unroll
            for (int mi = 0; mi < 4; mi++)
                #pragma unroll
                for (int ni = 0; ni < 4; ni++)
                    mma16816(acc[mi][ni], aH[mi], bH[ni]);
            #pragma unroll
            for (int mi = 0; mi < 4; mi++)
                #pragma unroll
                for (int ni = 0; ni < 4; ni++)
                    mma16816(acc[mi][ni], aH[mi], bL[ni]);
            #pragma unroll
            for (int mi = 0; mi < 4; mi++)
                #pragma unroll
                for (int ni = 0; ni < 4; ni++)
                    mma16816(acc[mi][ni], aL[mi], bH[ni]);
        }
        __syncthreads();
    }

    // ---- epilogue ----
    const int g = lid >> 2, c2 = (lid & 3) * 2;
    #pragma unroll
    for (int mi = 0; mi < 4; mi++) {
        #pragma unroll
        for (int ni = 0; ni < 4; ni++) {
            int row = m0 + wm + mi * 16 + g;
            int col = n0 + wn + ni * 8 + c2;
            float b0 = 0.f, b1 = 0.f;
            if (bias) { b0 = bias[col]; b1 = bias[col + 1]; }
            float2 o0 = { acc[mi][ni][0] + b0, acc[mi][ni][1] + b1 };
            float2 o1 = { acc[mi][ni][2] + b0, acc[mi][ni][3] + b1 };
            *(float2*)&C[(size_t)row * DIMV + col]       = o0;
            *(float2*)&C[(size_t)(row + 8) * DIMV + col] = o1;
        }
    }
}

// ---------------- KV accumulation ----------------
__global__ __launch_bounds__(256) void kv_accum(
    const float* __restrict__ kmat, const float* __restrict__ vmat,
    const float* __restrict__ Wr, const float* __restrict__ br)
{
    extern __shared__ float smf[];
    float* Wr_s = smf;
    float* br_s = Wr_s + 8192;
    float* k_s  = br_s + 128;
    float* v_s  = k_s + 1024;
    float* kf_s = v_s + 1024;

    const int tid = threadIdx.x;
    const int bh  = blockIdx.y;
    const int b   = bh >> 4, h = bh & 15;
    const int chunk = SEQ / NCHUNK;
    const int n0 = blockIdx.x * chunk;

    const float* WrH = Wr + (size_t)h * DK * RFF;
    for (int i = tid; i < 2048; i += 256)
        *(float4*)&Wr_s[i * 4] = *(const float4*)&WrH[i * 4];
    if (tid < 128) br_s[tid] = br[h * RFF + tid];

    const int f_grp = tid >> 3;
    const int d_grp = tid & 7;
    const int pn = tid >> 4;
    const int rb = (tid & 15) << 3;

    float acc[8][8];
    #pragma unroll
    for (int i = 0; i < 8; i++)
        #pragma unroll
        for (int j = 0; j < 8; j++) acc[i][j] = 0.f;
    float ksacc[8] = {0, 0, 0, 0, 0, 0, 0, 0};

    const float* kbase = kmat + (size_t)(b * SEQ + n0) * DIMV + h * DK;
    const float* vbase = vmat + (size_t)(b * SEQ + n0) * DIMV + h * DK;

    __syncthreads();

    for (int nn = 0; nn < chunk; nn += 16) {
        {
            int row = tid >> 4, c = (tid & 15) << 2;
            *(float4*)&k_s[row * 64 + c] = *(const float4*)&kbase[(size_t)(nn + row) * DIMV + c];
            *(float4*)&v_s[row * 64 + c] = *(const float4*)&vbase[(size_t)(nn + row) * DIMV + c];
        }
        __syncthreads();
        {
            float p[8];
            #pragma unroll
            for (int j = 0; j < 8; j++) p[j] = br_s[rb + j];
            #pragma unroll 8
            for (int d = 0; d < 64; d++) {
                float kv = k_s[pn * 64 + d];
                float4 w0 = *(float4*)&Wr_s[d * 128 + rb];
                float4 w1 = *(float4*)&Wr_s[d * 128 + rb + 4];
                p[0] += kv * w0.x; p[1] += kv * w0.y; p[2] += kv * w0.z; p[3] += kv * w0.w;
                p[4] += kv * w1.x; p[5] += kv * w1.y; p[6] += kv * w1.z; p[7] += kv * w1.w;
            }
            #pragma unroll
            for (int j = 0; j < 8; j++) {
                float sv, cv;
                __sincosf(p[j], &sv, &cv);
                kf_s[pn * 256 + rb + j]       = cv * INV_SQRT_R;
                kf_s[pn * 256 + 128 + rb + j] = sv * INV_SQRT_R;
            }
        }
        __syncthreads();
        #pragma unroll
        for (int kk = 0; kk < 16; kk++) {
            float a[8], bb[8];
            *(float4*)&a[0] = *(float4*)&kf_s[kk * 256 + f_grp * 8];
            *(float4*)&a[4] = *(float4*)&kf_s[kk * 256 + f_grp * 8 + 4];
            *(float4*)&bb[0] = *(float4*)&v_s[kk * 64 + d_grp * 8];
            *(float4*)&bb[4] = *(float4*)&v_s[kk * 64 + d_grp * 8 + 4];
            #pragma unroll
            for (int i = 0; i < 8; i++)
                #pragma unroll
                for (int j = 0; j < 8; j++)
                    acc[i][j] += a[i] * bb[j];
            if (d_grp == 0) {
                #pragma unroll
                for (int i = 0; i < 8; i++) ksacc[i] += a[i];
            }
        }
        __syncthreads();
    }

    float* dst = g_kv_part + ((size_t)blockIdx.x * 32 + bh) * FEAT * DK;
    #pragma unroll
    for (int i = 0; i < 8; i++)
        #pragma unroll
        for (int j = 0; j < 8; j++)
            dst[(f_grp * 8 + i) * DK + d_grp * 8 + j] = acc[i][j];
    if (d_grp == 0) {
        float* kd = g_ksum_part + ((size_t)blockIdx.x * 32 + bh) * FEAT;
        #pragma unroll
        for (int i = 0; i < 8; i++) kd[f_grp * 8 + i] = ksacc[i];
    }
}

__global__ __launch_bounds__(256) void kv_reduce()
{
    int i = blockIdx.x * 256 + threadIdx.x;
    if (i < BATCH * NHEADS * FEAT * DK) {
        int bh = i / (FEAT * DK);
        int e  = i % (FEAT * DK);
        float s = 0.f;
        #pragma unroll
        for (int c = 0; c < NCHUNK; c++)
            s += g_kv_part[((size_t)c * 32 + bh) * FEAT * DK + e];
        g_kv[i] = s;
    }
    if (i < BATCH * NHEADS * FEAT) {
        int bh = i / FEAT;
        int e  = i % FEAT;
        float s = 0.f;
        #pragma unroll
        for (int c = 0; c < NCHUNK; c++)
            s += g_ksum_part[((size_t)c * 32 + bh) * FEAT + e];
        g_ksum[i] = s;
    }
}

// ---------------- query side ----------------
__global__ __launch_bounds__(256) void attn_out(
    const float* __restrict__ qmat,
    const float* __restrict__ Wr, const float* __restrict__ br)
{
    extern __shared__ float smf[];
    float* Wr_s   = smf;
    float* br_s   = Wr_s + 8192;
    float* ksum_s = br_s + 128;
    float* Kv_s   = ksum_s + 256;
    float* q_s    = Kv_s + 16384;
    float* qf_s   = q_s + 1024;
    float* z_s    = qf_s + 4096;

    const int tid = threadIdx.x;
    const int bh  = blockIdx.y;
    const int b   = bh >> 4, h = bh & 15;
    const int rows0 = blockIdx.x * 128;

    const float* WrH = Wr + (size_t)h * DK * RFF;
    for (int i = tid; i < 2048; i += 256)
        *(float4*)&Wr_s[i * 4] = *(const float4*)&WrH[i * 4];
    if (tid < 128) br_s[tid] = br[h * RFF + tid];
    ksum_s[tid] = g_ksum[bh * FEAT + tid];
    {
        const float* KvB = g_kv + (size_t)bh * FEAT * DK;
        for (int i = tid; i < 4096; i += 256)
            *(float4*)&Kv_s[i * 4] = *(const float4*)&KvB[i * 4];
    }
    __syncthreads();

    const int pn = tid >> 4;
    const int rb = (tid & 15) << 3;

    const float* qbase = qmat + (size_t)(b * SEQ + rows0) * DIMV + h * DK;
    float* obase = g_attn + (size_t)(b * SEQ + rows0) * DIMV + h * DK;

    for (int ss = 0; ss < 128; ss += 16) {
        {
            int row = tid >> 4, c = (tid & 15) << 2;
            *(float4*)&q_s[row * 64 + c] = *(const float4*)&qbase[(size_t)(ss + row) * DIMV + c];
        }
        __syncthreads();
        {
            float p[8];
            #pragma unroll
            for (int j = 0; j < 8; j++) p[j] = br_s[rb + j];
            #pragma unroll 8
            for (int d = 0; d < 64; d++) {
                float qv = q_s[pn * 64 + d];
                float4 w0 = *(float4*)&Wr_s[d * 128 + rb];
                float4 w1 = *(float4*)&Wr_s[d * 128 + rb + 4];
                p[0] += qv * w0.x; p[1] += qv * w0.y; p[2] += qv * w0.z; p[3] += qv * w0.w;
                p[4] += qv * w1.x; p[5] += qv * w1.y; p[6] += qv * w1.z; p[7] += qv * w1.w;
            }
            #pragma unroll
            for (int j = 0; j < 8; j++) {
                float sv, cv;
                __sincosf(p[j], &sv, &cv);
                qf_s[pn * 256 + rb + j]       = cv * INV_SQRT_R;
                qf_s[pn * 256 + 128 + rb + j] = sv * INV_SQRT_R;
            }
        }
        __syncthreads();
        if (tid < 16) {
            float acc = 0.f;
            #pragma unroll 8
            for (int f = 0; f < FEAT; f++) acc += qf_s[tid * 256 + f] * ksum_s[f];
            z_s[tid] = 1.f / (acc + 1e-6f);
        }
        __syncthreads();
        {
            int row = tid >> 4, db = (tid & 15) << 2;
            float4 o = {0.f, 0.f, 0.f, 0.f};
            #pragma unroll 8
            for (int f = 0; f < FEAT; f++) {
                float qv = qf_s[row * 256 + f];
                float4 kv = *(float4*)&Kv_s[f * 64 + db];
                o.x += qv * kv.x; o.y += qv * kv.y; o.z += qv * kv.z; o.w += qv * kv.w;
            }
            float zz = z_s[row];
            o.x *= zz; o.y *= zz; o.z *= zz; o.w *= zz;
            *(float4*)&obase[(size_t)(ss + row) * DIMV + db] = o;
        }
        __syncthreads();
    }
}

// ---------------- launch ----------------
extern "C" void kernel_launch(void* const* d_in, const int* in_sizes, int n_in,
                              void* d_out, int out_size)
{
    const float* x  = (const float*)d_in[0];
    const float* Wq = (const float*)d_in[1];
    const float* Wk = (const float*)d_in[2];
    const float* Wv = (const float*)d_in[3];
    const float* Wp = (const float*)d_in[4];
    const float* bp = (const float*)d_in[5];
    const float* Wr = (const float*)d_in[6];
    const float* br = (const float*)d_in[7];
    float* out = (float*)d_out;

    float *qp, *kp, *vp, *ap;
    cudaGetSymbolAddress((void**)&qp, g_q);
    cudaGetSymbolAddress((void**)&kp, g_k);
    cudaGetSymbolAddress((void**)&vp, g_v);
    cudaGetSymbolAddress((void**)&ap, g_attn);
    __nv_bfloat16 *xh, *xl, *ah, *al, *wh, *wl;
    cudaGetSymbolAddress((void**)&xh, g_xh);
    cudaGetSymbolAddress((void**)&xl, g_xl);
    cudaGetSymbolAddress((void**)&ah, g_ah);
    cudaGetSymbolAddress((void**)&al, g_al);
    cudaGetSymbolAddress((void**)&wh, g_wh);
    cudaGetSymbolAddress((void**)&wl, g_wl);

    const int smem_kv   = 14464 * 4;
    const int smem_attn = 30096 * 4;
    cudaFuncSetAttribute(kv_accum, cudaFuncAttributeMaxDynamicSharedMemorySize, smem_kv);
    cudaFuncSetAttribute(attn_out, cudaFuncAttributeMaxDynamicSharedMemorySize, smem_attn);
    cudaFuncSetAttribute(gemm_bf16x3, cudaFuncAttributeMaxDynamicSharedMemorySize, GEMM_SMEM);

    const int WSZ = DIMV * DIMV;
    const int n4x = MROWS * DIMV / 4;
    const int n4w = WSZ / 4;

    split_bf16<<<(n4x + 255) / 256, 256>>>(x, xh, xl, n4x);
    split_bf16<<<(n4w + 255) / 256, 256>>>(Wq, wh + 0 * WSZ, wl + 0 * WSZ, n4w);
    split_bf16<<<(n4w + 255) / 256, 256>>>(Wk, wh + 1 * WSZ, wl + 1 * WSZ, n4w);
    split_bf16<<<(n4w + 255) / 256, 256>>>(Wv, wh + 2 * WSZ, wl + 2 * WSZ, n4w);
    split_bf16<<<(n4w + 255) / 256, 256>>>(Wp, wh + 3 * WSZ, wl + 3 * WSZ, n4w);

    dim3 gg(DIMV / 128, MROWS / 128);   // 8 x 128
    gemm_bf16x3<<<gg, 256, GEMM_SMEM>>>(xh, xl, wh + 0 * WSZ, wl + 0 * WSZ, nullptr, qp);
    gemm_bf16x3<<<gg, 256, GEMM_SMEM>>>(xh, xl, wh + 1 * WSZ, wl + 1 * WSZ, nullptr, kp);
    gemm_bf16x3<<<gg, 256, GEMM_SMEM>>>(xh, xl, wh + 2 * WSZ, wl + 2 * WSZ, nullptr, vp);

    kv_accum<<<dim3(NCHUNK, BATCH * NHEADS), 256, smem_kv>>>(kp, vp, Wr, br);
    kv_reduce<<<(BATCH * NHEADS * FEAT * DK + 255) / 256, 256>>>();
    attn_out<<<dim3(SEQ / 128, BATCH * NHEADS), 256, smem_attn>>>(qp, Wr, br);

    split_bf16<<<(n4x + 255) / 256, 256>>>(ap, ah, al, n4x);
    gemm_bf16x3<<<gg, 256, GEMM_SMEM>>>(ah, al, wh + 3 * WSZ, wl + 3 * WSZ, bp, out);
}

// round 4
// speedup vs baseline: 2.8667x; 1.9664x over previous
#include <cuda_runtime.h>
#include <cuda_bf16.h>
#include <math.h>
#include <stdint.h>

#define DIMV 1024
#define NHEADS 16
#define DK 64
#define RFF 128
#define FEAT 256
#define BATCH 2
#define SEQ 8192
#define MROWS 16384
#define BH 32
#define NPAD 96
#define INV_SQRT_R 0.08838834764831845f

typedef __nv_bfloat16 bf16;
typedef __nv_bfloat162 bf162;

// ---------------- scratch (device globals) ----------------
__device__ bf16 g_xh[MROWS*DIMV], g_xl[MROWS*DIMV];
__device__ bf16 g_wh[4*DIMV*DIMV], g_wl[4*DIMV*DIMV];
__device__ bf16 g_qh[MROWS*DIMV], g_ql[MROWS*DIMV];
__device__ bf16 g_kh[MROWS*DIMV], g_kl[MROWS*DIMV];
__device__ bf16 g_vth[BH*NPAD*SEQ], g_vtl[BH*NPAD*SEQ];
__device__ bf16 g_wrth[NHEADS*RFF*DK], g_wrtl[NHEADS*RFF*DK];
__device__ bf16 g_qfh[(size_t)BH*SEQ*FEAT], g_qfl[(size_t)BH*SEQ*FEAT];
__device__ bf16 g_kfh[(size_t)BH*FEAT*SEQ], g_kfl[(size_t)BH*FEAT*SEQ];
__device__ float g_kvp[8*BH*FEAT*NPAD];
__device__ bf16 g_dth[BH*NPAD*FEAT], g_dtl[BH*NPAD*FEAT];
__device__ bf16 g_ah[MROWS*DIMV], g_al[MROWS*DIMV];

// ---------------- helpers ----------------
__device__ __forceinline__ uint32_t smem_u32(const void* p) {
    uint32_t a;
    asm("{ .reg .u64 t; cvta.to.shared.u64 t, %1; cvt.u32.u64 %0, t; }" : "=r"(a) : "l"(p));
    return a;
}
__device__ __forceinline__ void cpa16(uint32_t s, const void* g) {
    asm volatile("cp.async.cg.shared.global [%0], [%1], 16;" :: "r"(s), "l"(g));
}
__device__ __forceinline__ void cpa_commit() { asm volatile("cp.async.commit_group;"); }
__device__ __forceinline__ void ldmx4(uint32_t addr, uint32_t& r0, uint32_t& r1, uint32_t& r2, uint32_t& r3) {
    asm volatile("ldmatrix.sync.aligned.m8n8.x4.shared.b16 {%0,%1,%2,%3}, [%4];"
                 : "=r"(r0), "=r"(r1), "=r"(r2), "=r"(r3) : "r"(addr));
}
__device__ __forceinline__ void mma16816(float* d, const uint32_t* a, const uint32_t* b) {
    asm volatile(
        "mma.sync.aligned.m16n8k16.row.col.f32.bf16.bf16.f32 "
        "{%0,%1,%2,%3}, {%4,%5,%6,%7}, {%8,%9}, {%0,%1,%2,%3};"
        : "+f"(d[0]), "+f"(d[1]), "+f"(d[2]), "+f"(d[3])
        : "r"(a[0]), "r"(a[1]), "r"(a[2]), "r"(a[3]), "r"(b[0]), "r"(b[1]));
}
__device__ __forceinline__ void bsplit(float v, bf16& h, bf16& l) {
    h = __float2bfloat16(v);
    l = __float2bfloat16(v - __bfloat162float(h));
}
__device__ __forceinline__ bf162 mk2(bf16 a, bf16 b) { bf162 t; t.x = a; t.y = b; return t; }

// ---------------- fp32 -> (hi, lo) bf16 split ----------------
__global__ __launch_bounds__(256) void split_bf16(
    const float* __restrict__ in, bf16* __restrict__ hi, bf16* __restrict__ lo, int n4)
{
    int i = blockIdx.x * 256 + threadIdx.x;
    if (i >= n4) return;
    float4 v = ((const float4*)in)[i];
    bf16 h0, l0, h1, l1, h2, l2, h3, l3;
    bsplit(v.x, h0, l0); bsplit(v.y, h1, l1); bsplit(v.z, h2, l2); bsplit(v.w, h3, l3);
    ((bf162*)hi)[2*i]   = mk2(h0, h1);
    ((bf162*)hi)[2*i+1] = mk2(h2, h3);
    ((bf162*)lo)[2*i]   = mk2(l0, l1);
    ((bf162*)lo)[2*i+1] = mk2(l2, l3);
}

// ---------------- WrT prep: WrT[h][r][j] = Wr[h][j][r], split ----------------
__global__ __launch_bounds__(256) void prep_wrt(const float* __restrict__ Wr)
{
    int h = blockIdx.x;
    for (int e = threadIdx.x; e < RFF * DK; e += 256) {
        int r = e >> 6, j = e & 63;
        float v = Wr[(size_t)h * DK * RFF + j * RFF + r];
        bf16 hi, lo; bsplit(v, hi, lo);
        g_wrth[h * RFF * DK + e] = hi;
        g_wrtl[h * RFF * DK + e] = lo;
    }
}

// ---------------- vT padding rows: d=64 -> ones, 65..95 -> zeros ----------------
__global__ __launch_bounds__(256) void fill_vt()
{
    int bx = blockIdx.x;                 // 0..1023
    int bh = bx >> 5, dr = 64 + (bx & 31);
    bf16 v = __float2bfloat16(dr == 64 ? 1.f : 0.f);
    bf16 z = __float2bfloat16(0.f);
    bf162 vv = mk2(v, v), zz = mk2(z, z);
    size_t base = ((size_t)bh * NPAD + dr) * SEQ;
    for (int i = threadIdx.x; i < SEQ / 2; i += 256) {
        *(bf162*)&g_vth[base + 2 * i] = vv;
        *(bf162*)&g_vtl[base + 2 * i] = zz;
    }
}

// ---------------- big bf16x3 GEMM: C[M,1024] = A @ B^T ----------------
// MODE 0: fp32 + bias; MODE 1: bf16 hi/lo same layout; MODE 2: per-head transposed vT hi/lo.
#define GSTAGE 32768
#define GEMM_SMEM (2 * GSTAGE)

template<int MODE>
__global__ __launch_bounds__(256, 1) void gemm_bf16x3(
    const bf16* __restrict__ Ah, const bf16* __restrict__ Al,
    const bf16* __restrict__ Bh, const bf16* __restrict__ Bl,
    const float* __restrict__ bias, float* __restrict__ C,
    bf16* __restrict__ Ch, bf16* __restrict__ Cl)
{
    extern __shared__ __align__(128) char sm[];
    const int tid = threadIdx.x, wid = tid >> 5, lid = tid & 31;
    const int m0 = blockIdx.y * 128, n0 = blockIdx.x * 128;
    const int wm = (wid & 1) * 64;
    const int wn = (wid >> 1) * 32;
    const uint32_t smb = smem_u32(sm);

    float acc[4][4][4];
    #pragma unroll
    for (int i = 0; i < 4; i++)
        #pragma unroll
        for (int j = 0; j < 4; j++)
            #pragma unroll
            for (int e = 0; e < 4; e++) acc[i][j][e] = 0.f;

    auto load_stage = [&](int ci, int s) {
        const int k0 = ci * 32;
        const uint32_t sb = smb + s * GSTAGE;
        #pragma unroll
        for (int it = 0; it < 2; it++) {
            int t = tid + it * 256;
            int row = t >> 2, q = t & 3;
            uint32_t soff = row * 64 + ((q ^ ((row >> 1) & 3)) << 4);
            size_t ga = (size_t)(m0 + row) * DIMV + k0 + q * 8;
            size_t gb = (size_t)(n0 + row) * DIMV + k0 + q * 8;
            cpa16(sb + soff,         Ah + ga);
            cpa16(sb + 8192  + soff, Al + ga);
            cpa16(sb + 16384 + soff, Bh + gb);
            cpa16(sb + 24576 + soff, Bl + gb);
        }
        cpa_commit();
    };

    load_stage(0, 0);

    #pragma unroll 1
    for (int ci = 0; ci < 32; ci++) {
        const int s = ci & 1;
        if (ci < 31) { load_stage(ci + 1, s ^ 1); asm volatile("cp.async.wait_group 1;"); }
        else         asm volatile("cp.async.wait_group 0;");
        __syncthreads();

        const uint32_t sb = smb + s * GSTAGE;
        #pragma unroll
        for (int ks = 0; ks < 2; ks++) {
            uint32_t aH[4][4], aL[4][4], bH[4][2], bL[4][2];
            #pragma unroll
            for (int mi = 0; mi < 4; mi++) {
                int row = wm + mi * 16 + (lid & 7) + ((lid >> 3) & 1) * 8;
                int q = ks * 2 + (lid >> 4);
                uint32_t off = row * 64 + ((q ^ ((row >> 1) & 3)) << 4);
                ldmx4(sb + off,        aH[mi][0], aH[mi][1], aH[mi][2], aH[mi][3]);
                ldmx4(sb + 8192 + off, aL[mi][0], aL[mi][1], aL[mi][2], aL[mi][3]);
            }
            #pragma unroll
            for (int np = 0; np < 2; np++) {
                int row = wn + np * 16 + (lid >> 4) * 8 + (lid & 7);
                int q = ks * 2 + ((lid >> 3) & 1);
                uint32_t off = row * 64 + ((q ^ ((row >> 1) & 3)) << 4);
                ldmx4(sb + 16384 + off, bH[2*np][0], bH[2*np][1], bH[2*np+1][0], bH[2*np+1][1]);
                ldmx4(sb + 24576 + off, bL[2*np][0], bL[2*np][1], bL[2*np+1][0], bL[2*np+1][1]);
            }
            #pragma unroll
            for (int mi = 0; mi < 4; mi++)
                #pragma unroll
                for (int ni = 0; ni < 4; ni++)
                    mma16816(acc[mi][ni], aH[mi], bH[ni]);
            #pragma unroll
            for (int mi = 0; mi < 4; mi++)
                #pragma unroll
                for (int ni = 0; ni < 4; ni++)
                    mma16816(acc[mi][ni], aH[mi], bL[ni]);
            #pragma unroll
            for (int mi = 0; mi < 4; mi++)
                #pragma unroll
                for (int ni = 0; ni < 4; ni++)
                    mma16816(acc[mi][ni], aL[mi], bH[ni]);
        }
        __syncthreads();
    }

    const int g = lid >> 2, c2 = (lid & 3) * 2;
    #pragma unroll
    for (int mi = 0; mi < 4; mi++) {
        #pragma unroll
        for (int ni = 0; ni < 4; ni++) {
            int row = m0 + wm + mi * 16 + g;
            int col = n0 + wn + ni * 8 + c2;
            if (MODE == 0) {
                float b0 = bias ? bias[col] : 0.f;
                float b1 = bias ? bias[col + 1] : 0.f;
                float2 o0 = { acc[mi][ni][0] + b0, acc[mi][ni][1] + b1 };
                float2 o1 = { acc[mi][ni][2] + b0, acc[mi][ni][3] + b1 };
                *(float2*)&C[(size_t)row * DIMV + col]       = o0;
                *(float2*)&C[(size_t)(row + 8) * DIMV + col] = o1;
            } else if (MODE == 1) {
                bf16 h0, l0, h1, l1;
                bsplit(acc[mi][ni][0], h0, l0); bsplit(acc[mi][ni][1], h1, l1);
                *(bf162*)&Ch[(size_t)row * DIMV + col] = mk2(h0, h1);
                *(bf162*)&Cl[(size_t)row * DIMV + col] = mk2(l0, l1);
                bsplit(acc[mi][ni][2], h0, l0); bsplit(acc[mi][ni][3], h1, l1);
                *(bf162*)&Ch[(size_t)(row + 8) * DIMV + col] = mk2(h0, h1);
                *(bf162*)&Cl[(size_t)(row + 8) * DIMV + col] = mk2(l0, l1);
            } else {
                int hh = col >> 6, d0 = col & 63;
                int b = row >> 13, n = row & 8191;
                size_t base = ((size_t)(b * NHEADS + hh) * NPAD) * SEQ;
                bf16 h0, l0;
                bsplit(acc[mi][ni][0], h0, l0);
                Ch[base + (size_t)d0 * SEQ + n] = h0;       Cl[base + (size_t)d0 * SEQ + n] = l0;
                bsplit(acc[mi][ni][1], h0, l0);
                Ch[base + (size_t)(d0+1) * SEQ + n] = h0;   Cl[base + (size_t)(d0+1) * SEQ + n] = l0;
                bsplit(acc[mi][ni][2], h0, l0);
                Ch[base + (size_t)d0 * SEQ + n + 8] = h0;   Cl[base + (size_t)d0 * SEQ + n + 8] = l0;
                bsplit(acc[mi][ni][3], h0, l0);
                Ch[base + (size_t)(d0+1) * SEQ + n + 8] = h0; Cl[base + (size_t)(d0+1) * SEQ + n + 8] = l0;
            }
        }
    }
}

// ---------------- proj + RFF features: per (head, qk) ----------------
// C[n, r] = q[n, h*64..] @ WrT[h]^T ; epilogue: +br, sincos, scale, split, store qf/kf.
#define PROJ_SMEM 65536

__global__ __launch_bounds__(256, 1) void proj_feat(const float* __restrict__ brp)
{
    extern __shared__ __align__(128) char sm[];
    const int tid = threadIdx.x, wid = tid >> 5, lid = tid & 31;
    const int m0 = blockIdx.x * 128;
    const int qk = blockIdx.y >> 4, h = blockIdx.y & 15;
    const int wm = (wid & 1) * 64, wn = (wid >> 1) * 32;
    const uint32_t smb = smem_u32(sm);

    const bf16* Ah = (qk ? g_kh : g_qh);
    const bf16* Al = (qk ? g_kl : g_ql);
    const bf16* Bh = g_wrth + h * RFF * DK;
    const bf16* Bl = g_wrtl + h * RFF * DK;

    // load A[128x64] and B[128x64] hi/lo, 128B rows, swizzle q ^ (row & 7)
    #pragma unroll
    for (int it = 0; it < 4; it++) {
        int idx = tid + it * 256;          // 0..1023
        int row = idx >> 3, q = idx & 7;
        uint32_t soff = row * 128 + ((q ^ (row & 7)) << 4);
        *(uint4*)(sm + soff)         = *(const uint4*)(Ah + (size_t)(m0 + row) * DIMV + h * DK + q * 8);
        *(uint4*)(sm + 16384 + soff) = *(const uint4*)(Al + (size_t)(m0 + row) * DIMV + h * DK + q * 8);
        *(uint4*)(sm + 32768 + soff) = *(const uint4*)(Bh + row * DK + q * 8);
        *(uint4*)(sm + 49152 + soff) = *(const uint4*)(Bl + row * DK + q * 8);
    }
    __syncthreads();

    float acc[4][4][4];
    #pragma unroll
    for (int i = 0; i < 4; i++)
        #pragma unroll
        for (int j = 0; j < 4; j++)
            #pragma unroll
            for (int e = 0; e < 4; e++) acc[i][j][e] = 0.f;

    #pragma unroll
    for (int ks = 0; ks < 4; ks++) {
        uint32_t aH[4][4], aL[4][4], bH[4][2], bL[4][2];
        #pragma unroll
        for (int mi = 0; mi < 4; mi++) {
            int row = wm + mi * 16 + (lid & 7) + ((lid >> 3) & 1) * 8;
            int q = ks * 2 + (lid >> 4);
            uint32_t off = row * 128 + ((q ^ (row & 7)) << 4);
            ldmx4(smb + off,         aH[mi][0], aH[mi][1], aH[mi][2], aH[mi][3]);
            ldmx4(smb + 16384 + off, aL[mi][0], aL[mi][1], aL[mi][2], aL[mi][3]);
        }
        #pragma unroll
        for (int np = 0; np < 2; np++) {
            int row = wn + np * 16 + (lid >> 4) * 8 + (lid & 7);
            int q = ks * 2 + ((lid >> 3) & 1);
            uint32_t off = row * 128 + ((q ^ (row & 7)) << 4);
            ldmx4(smb + 32768 + off, bH[2*np][0], bH[2*np][1], bH[2*np+1][0], bH[2*np+1][1]);
            ldmx4(smb + 49152 + off, bL[2*np][0], bL[2*np][1], bL[2*np+1][0], bL[2*np+1][1]);
        }
        #pragma unroll
        for (int mi = 0; mi < 4; mi++)
            #pragma unroll
            for (int ni = 0; ni < 4; ni++) {
                mma16816(acc[mi][ni], aH[mi], bH[ni]);
                mma16816(acc[mi][ni], aH[mi], bL[ni]);
                mma16816(acc[mi][ni], aL[mi], bH[ni]);
            }
    }

    // epilogue: features
    const int g = lid >> 2, c2 = (lid & 3) * 2;
    #pragma unroll
    for (int mi = 0; mi < 4; mi++) {
        #pragma unroll
        for (int ni = 0; ni < 4; ni++) {
            int col = wn + ni * 8 + c2;               // r, r+1
            float b0 = brp[h * RFF + col], b1 = brp[h * RFF + col + 1];
            #pragma unroll
            for (int half = 0; half < 2; half++) {
                int row = m0 + wm + mi * 16 + g + half * 8;
                int b = row >> 13, n = row & 8191;
                int bh = b * NHEADS + h;
                float p0 = acc[mi][ni][half * 2 + 0] + b0;
                float p1 = acc[mi][ni][half * 2 + 1] + b1;
                float s0, c0, s1, c1;
                __sincosf(p0, &s0, &c0);
                __sincosf(p1, &s1, &c1);
                c0 *= INV_SQRT_R; s0 *= INV_SQRT_R;
                c1 *= INV_SQRT_R; s1 *= INV_SQRT_R;
                bf16 ch0, cl0, ch1, cl1, sh0, sl0, sh1, sl1;
                bsplit(c0, ch0, cl0); bsplit(c1, ch1, cl1);
                bsplit(s0, sh0, sl0); bsplit(s1, sh1, sl1);
                if (qk == 0) {
                    size_t base = ((size_t)bh * SEQ + n) * FEAT;
                    *(bf162*)&g_qfh[base + col]       = mk2(ch0, ch1);
                    *(bf162*)&g_qfl[base + col]       = mk2(cl0, cl1);
                    *(bf162*)&g_qfh[base + RFF + col] = mk2(sh0, sh1);
                    *(bf162*)&g_qfl[base + RFF + col] = mk2(sl0, sl1);
                } else {
                    size_t kb = ((size_t)bh * FEAT + col) * SEQ + n;
                    g_kfh[kb] = ch0;              g_kfl[kb] = cl0;
                    g_kfh[kb + SEQ] = ch1;        g_kfl[kb + SEQ] = cl1;
                    g_kfh[kb + (size_t)RFF*SEQ] = sh0;        g_kfl[kb + (size_t)RFF*SEQ] = sl0;
                    g_kfh[kb + (size_t)(RFF+1)*SEQ] = sh1;    g_kfl[kb + (size_t)(RFF+1)*SEQ] = sl1;
                }
            }
        }
    }
}

// ---------------- Kv GEMM (split-K): C[f, d] = sum_n kf[f,n] * vT[d,n] ----------------
// grid (8 kslices, bh*2+m2), block 256. M=128, N=96, BK=32, 32 iters.
#define KV_STG 28672
#define KV_SMEM (2 * KV_STG)

__global__ __launch_bounds__(256, 1) void gemm_kv()
{
    extern __shared__ __align__(128) char sm[];
    const int tid = threadIdx.x, wid = tid >> 5, lid = tid & 31;
    const int ks = blockIdx.x;
    const int bh = blockIdx.y >> 1, m2 = blockIdx.y & 1;
    const int wm = (wid & 3) * 32, wn = (wid >> 2) * 48;
    const uint32_t smb = smem_u32(sm);

    const bf16* Ah = g_kfh + ((size_t)bh * FEAT + m2 * 128) * SEQ + ks * 1024;
    const bf16* Al = g_kfl + ((size_t)bh * FEAT + m2 * 128) * SEQ + ks * 1024;
    const bf16* Bhp = g_vth + (size_t)bh * NPAD * SEQ + ks * 1024;
    const bf16* Blp = g_vtl + (size_t)bh * NPAD * SEQ + ks * 1024;

    float acc[2][6][4];
    #pragma unroll
    for (int i = 0; i < 2; i++)
        #pragma unroll
        for (int j = 0; j < 6; j++)
            #pragma unroll
            for (int e = 0; e < 4; e++) acc[i][j][e] = 0.f;

    auto load_stage = [&](int ci, int s) {
        const int k0 = ci * 32;
        const uint32_t sb = smb + s * KV_STG;
        #pragma unroll
        for (int it = 0; it < 2; it++) {
            int idx = tid + it * 256;
            int row = idx >> 2, q = idx & 3;
            uint32_t soff = row * 64 + ((q ^ ((row >> 1) & 3)) << 4);
            cpa16(sb + soff,        Ah + (size_t)row * SEQ + k0 + q * 8);
            cpa16(sb + 8192 + soff, Al + (size_t)row * SEQ + k0 + q * 8);
        }
        for (int idx = tid; idx < 384; idx += 256) {
            int row = idx >> 2, q = idx & 3;
            uint32_t soff = row * 64 + ((q ^ ((row >> 1) & 3)) << 4);
            cpa16(sb + 16384 + soff, Bhp + (size_t)row * SEQ + k0 + q * 8);
            cpa16(sb + 22528 + soff, Blp + (size_t)row * SEQ + k0 + q * 8);
        }
        cpa_commit();
    };

    load_stage(0, 0);
    #pragma unroll 1
    for (int ci = 0; ci < 32; ci++) {
        const int s = ci & 1;
        if (ci < 31) { load_stage(ci + 1, s ^ 1); asm volatile("cp.async.wait_group 1;"); }
        else         asm volatile("cp.async.wait_group 0;");
        __syncthreads();
        const uint32_t sb = smb + s * KV_STG;
        #pragma unroll
        for (int k2 = 0; k2 < 2; k2++) {
            uint32_t aH[2][4], aL[2][4], bH[6][2], bL[6][2];
            #pragma unroll
            for (int mi = 0; mi < 2; mi++) {
                int row = wm + mi * 16 + (lid & 7) + ((lid >> 3) & 1) * 8;
                int q = k2 * 2 + (lid >> 4);
                uint32_t off = row * 64 + ((q ^ ((row >> 1) & 3)) << 4);
                ldmx4(sb + off,        aH[mi][0], aH[mi][1], aH[mi][2], aH[mi][3]);
                ldmx4(sb + 8192 + off, aL[mi][0], aL[mi][1], aL[mi][2], aL[mi][3]);
            }
            #pragma unroll
            for (int np = 0; np < 3; np++) {
                int row = wn + np * 16 + (lid >> 4) * 8 + (lid & 7);
                int q = k2 * 2 + ((lid >> 3) & 1);
                uint32_t off = row * 64 + ((q ^ ((row >> 1) & 3)) << 4);
                ldmx4(sb + 16384 + off, bH[2*np][0], bH[2*np][1], bH[2*np+1][0], bH[2*np+1][1]);
                ldmx4(sb + 22528 + off, bL[2*np][0], bL[2*np][1], bL[2*np+1][0], bL[2*np+1][1]);
            }
            #pragma unroll
            for (int mi = 0; mi < 2; mi++)
                #pragma unroll
                for (int ni = 0; ni < 6; ni++) {
                    mma16816(acc[mi][ni], aH[mi], bH[ni]);
                    mma16816(acc[mi][ni], aH[mi], bL[ni]);
                    mma16816(acc[mi][ni], aL[mi], bH[ni]);
                }
        }
        __syncthreads();
    }

    const int g = lid >> 2, c2 = (lid & 3) * 2;
    #pragma unroll
    for (int mi = 0; mi < 2; mi++) {
        #pragma unroll
        for (int ni = 0; ni < 6; ni++) {
            int rl = wm + mi * 16 + g;
            int col = wn + ni * 8 + c2;
            float* dp = g_kvp + (((size_t)ks * BH + bh) * FEAT + m2 * 128 + rl) * NPAD + col;
            float2 o0 = { acc[mi][ni][0], acc[mi][ni][1] };
            float2 o1 = { acc[mi][ni][2], acc[mi][ni][3] };
            *(float2*)dp = o0;
            *(float2*)(dp + 8 * NPAD) = o1;
        }
    }
}

// ---------------- reduce partials + transpose + split ----------------
__global__ __launch_bounds__(256) void kv_reduce_t()
{
    int i = blockIdx.x * 256 + threadIdx.x;
    if (i >= BH * FEAT * NPAD) return;
    int bh = i / (FEAT * NPAD);
    int rem = i - bh * FEAT * NPAD;
    int f = rem / NPAD, d = rem - f * NPAD;
    float s = 0.f;
    #pragma unroll
    for (int ks = 0; ks < 8; ks++)
        s += g_kvp[(((size_t)ks * BH + bh) * FEAT + f) * NPAD + d];
    bf16 hi, lo; bsplit(s, hi, lo);
    g_dth[((size_t)bh * NPAD + d) * FEAT + f] = hi;
    g_dtl[((size_t)bh * NPAD + d) * FEAT + f] = lo;
}

// ---------------- out GEMM: C[n, d] = sum_f qf[n,f] * Dt[d,f], z scaling ----------------
// grid (64 ntiles, 32 bh). M=128, N=96, BK=32, 8 iters. col 64 = denominator.
#define OUT_SMEM (2 * KV_STG + 512)

__global__ __launch_bounds__(256, 1) void gemm_out()
{
    extern __shared__ __align__(128) char sm[];
    const int tid = threadIdx.x, wid = tid >> 5, lid = tid & 31;
    const int n0 = blockIdx.x * 128;
    const int bh = blockIdx.y;
    const int wm = (wid & 3) * 32, wn = (wid >> 2) * 48;
    const uint32_t smb = smem_u32(sm);
    float* sden = (float*)(sm + 2 * KV_STG);

    const bf16* Ah = g_qfh + ((size_t)bh * SEQ + n0) * FEAT;
    const bf16* Al = g_qfl + ((size_t)bh * SEQ + n0) * FEAT;
    const bf16* Bhp = g_dth + (size_t)bh * NPAD * FEAT;
    const bf16* Blp = g_dtl + (size_t)bh * NPAD * FEAT;

    float acc[2][6][4];
    #pragma unroll
    for (int i = 0; i < 2; i++)
        #pragma unroll
        for (int j = 0; j < 6; j++)
            #pragma unroll
            for (int e = 0; e < 4; e++) acc[i][j][e] = 0.f;

    auto load_stage = [&](int ci, int s) {
        const int k0 = ci * 32;
        const uint32_t sb = smb + s * KV_STG;
        #pragma unroll
        for (int it = 0; it < 2; it++) {
            int idx = tid + it * 256;
            int row = idx >> 2, q = idx & 3;
            uint32_t soff = row * 64 + ((q ^ ((row >> 1) & 3)) << 4);
            cpa16(sb + soff,        Ah + (size_t)row * FEAT + k0 + q * 8);
            cpa16(sb + 8192 + soff, Al + (size_t)row * FEAT + k0 + q * 8);
        }
        for (int idx = tid; idx < 384; idx += 256) {
            int row = idx >> 2, q = idx & 3;
            uint32_t soff = row * 64 + ((q ^ ((row >> 1) & 3)) << 4);
            cpa16(sb + 16384 + soff, Bhp + (size_t)row * FEAT + k0 + q * 8);
            cpa16(sb + 22528 + soff, Blp + (size_t)row * FEAT + k0 + q * 8);
        }
        cpa_commit();
    };

    load_stage(0, 0);
    #pragma unroll 1
    for (int ci = 0; ci < 8; ci++) {
        const int s = ci & 1;
        if (ci < 7) { load_stage(ci + 1, s ^ 1); asm volatile("cp.async.wait_group 1;"); }
        else        asm volatile("cp.async.wait_group 0;");
        __syncthreads();
        const uint32_t sb = smb + s * KV_STG;
        #pragma unroll
        for (int k2 = 0; k2 < 2; k2++) {
            uint32_t aH[2][4], aL[2][4], bH[6][2], bL[6][2];
            #pragma unroll
            for (int mi = 0; mi < 2; mi++) {
                int row = wm + mi * 16 + (lid & 7) + ((lid >> 3) & 1) * 8;
                int q = k2 * 2 + (lid >> 4);
                uint32_t off = row * 64 + ((q ^ ((row >> 1) & 3)) << 4);
                ldmx4(sb + off,        aH[mi][0], aH[mi][1], aH[mi][2], aH[mi][3]);
                ldmx4(sb + 8192 + off, aL[mi][0], aL[mi][1], aL[mi][2], aL[mi][3]);
            }
            #pragma unroll
            for (int np = 0; np < 3; np++) {
                int row = wn + np * 16 + (lid >> 4) * 8 + (lid & 7);
                int q = k2 * 2 + ((lid >> 3) & 1);
                uint32_t off = row * 64 + ((q ^ ((row >> 1) & 3)) << 4);
                ldmx4(sb + 16384 + off, bH[2*np][0], bH[2*np][1], bH[2*np+1][0], bH[2*np+1][1]);
                ldmx4(sb + 22528 + off, bL[2*np][0], bL[2*np][1], bL[2*np+1][0], bL[2*np+1][1]);
            }
            #pragma unroll
            for (int mi = 0; mi < 2; mi++)
                #pragma unroll
                for (int ni = 0; ni < 6; ni++) {
                    mma16816(acc[mi][ni], aH[mi], bH[ni]);
                    mma16816(acc[mi][ni], aH[mi], bL[ni]);
                    mma16816(acc[mi][ni], aL[mi], bH[ni]);
                }
        }
        __syncthreads();
    }

    const int g = lid >> 2, c2 = (lid & 3) * 2;
    // denominator: col 64 lives in warps with wn==48, ni=2, c2==0
    if ((wid >> 2) == 1 && (lid & 3) == 0) {
        #pragma unroll
        for (int mi = 0; mi < 2; mi++) {
            int rl = wm + mi * 16 + g;
            sden[rl]     = acc[mi][2][0];
            sden[rl + 8] = acc[mi][2][2];
        }
    }
    __syncthreads();

    const int b = bh >> 4, h = bh & 15;
    const int nlim = ((wid >> 2) == 0) ? 6 : 2;
    #pragma unroll
    for (int mi = 0; mi < 2; mi++) {
        int rl = wm + mi * 16 + g;
        float z0 = 1.f / (sden[rl] + 1e-6f);
        float z1 = 1.f / (sden[rl + 8] + 1e-6f);
        size_t rg0 = (size_t)(b * SEQ + n0 + rl) * DIMV + h * 64;
        size_t rg1 = rg0 + 8 * DIMV;
        for (int ni = 0; ni < nlim; ni++) {
            int col = wn + ni * 8 + c2;
            bf16 h0, l0, h1, l1;
            bsplit(acc[mi][ni][0] * z0, h0, l0); bsplit(acc[mi][ni][1] * z0, h1, l1);
            *(bf162*)&g_ah[rg0 + col] = mk2(h0, h1);
            *(bf162*)&g_al[rg0 + col] = mk2(l0, l1);
            bsplit(acc[mi][ni][2] * z1, h0, l0); bsplit(acc[mi][ni][3] * z1, h1, l1);
            *(bf162*)&g_ah[rg1 + col] = mk2(h0, h1);
            *(bf162*)&g_al[rg1 + col] = mk2(l0, l1);
        }
    }
}

// ---------------- launch ----------------
extern "C" void kernel_launch(void* const* d_in, const int* in_sizes, int n_in,
                              void* d_out, int out_size)
{
    const float* x  = (const float*)d_in[0];
    const float* Wq = (const float*)d_in[1];
    const float* Wk = (const float*)d_in[2];
    const float* Wv = (const float*)d_in[3];
    const float* Wp = (const float*)d_in[4];
    const float* bp = (const float*)d_in[5];
    const float* Wr = (const float*)d_in[6];
    const float* br = (const float*)d_in[7];
    float* out = (float*)d_out;

    bf16 *xh, *xl, *wh, *wl, *qh, *ql, *kh, *kl, *vth, *vtl, *ah, *al;
    cudaGetSymbolAddress((void**)&xh, g_xh);   cudaGetSymbolAddress((void**)&xl, g_xl);
    cudaGetSymbolAddress((void**)&wh, g_wh);   cudaGetSymbolAddress((void**)&wl, g_wl);
    cudaGetSymbolAddress((void**)&qh, g_qh);   cudaGetSymbolAddress((void**)&ql, g_ql);
    cudaGetSymbolAddress((void**)&kh, g_kh);   cudaGetSymbolAddress((void**)&kl, g_kl);
    cudaGetSymbolAddress((void**)&vth, g_vth); cudaGetSymbolAddress((void**)&vtl, g_vtl);
    cudaGetSymbolAddress((void**)&ah, g_ah);   cudaGetSymbolAddress((void**)&al, g_al);

    cudaFuncSetAttribute(gemm_bf16x3<0>, cudaFuncAttributeMaxDynamicSharedMemorySize, GEMM_SMEM);
    cudaFuncSetAttribute(gemm_bf16x3<1>, cudaFuncAttributeMaxDynamicSharedMemorySize, GEMM_SMEM);
    cudaFuncSetAttribute(gemm_bf16x3<2>, cudaFuncAttributeMaxDynamicSharedMemorySize, GEMM_SMEM);
    cudaFuncSetAttribute(proj_feat, cudaFuncAttributeMaxDynamicSharedMemorySize, PROJ_SMEM);
    cudaFuncSetAttribute(gemm_kv,  cudaFuncAttributeMaxDynamicSharedMemorySize, KV_SMEM);
    cudaFuncSetAttribute(gemm_out, cudaFuncAttributeMaxDynamicSharedMemorySize, OUT_SMEM);

    const int WSZ = DIMV * DIMV;
    const int n4x = MROWS * DIMV / 4;
    const int n4w = WSZ / 4;

    split_bf16<<<(n4x + 255) / 256, 256>>>(x, xh, xl, n4x);
    split_bf16<<<(n4w + 255) / 256, 256>>>(Wq, wh + 0 * WSZ, wl + 0 * WSZ, n4w);
    split_bf16<<<(n4w + 255) / 256, 256>>>(Wk, wh + 1 * WSZ, wl + 1 * WSZ, n4w);
    split_bf16<<<(n4w + 255) / 256, 256>>>(Wv, wh + 2 * WSZ, wl + 2 * WSZ, n4w);
    split_bf16<<<(n4w + 255) / 256, 256>>>(Wp, wh + 3 * WSZ, wl + 3 * WSZ, n4w);
    prep_wrt<<<NHEADS, 256>>>(Wr);
    fill_vt<<<BH * 32, 256>>>();

    dim3 gg(DIMV / 128, MROWS / 128);
    gemm_bf16x3<1><<<gg, 256, GEMM_SMEM>>>(xh, xl, wh + 0*WSZ, wl + 0*WSZ, nullptr, nullptr, qh, ql);
    gemm_bf16x3<1><<<gg, 256, GEMM_SMEM>>>(xh, xl, wh + 1*WSZ, wl + 1*WSZ, nullptr, nullptr, kh, kl);
    gemm_bf16x3<2><<<gg, 256, GEMM_SMEM>>>(xh, xl, wh + 2*WSZ, wl + 2*WSZ, nullptr, nullptr, vth, vtl);

    proj_feat<<<dim3(MROWS / 128, 32), 256, PROJ_SMEM>>>(br);
    gemm_kv<<<dim3(8, BH * 2), 256, KV_SMEM>>>();
    kv_reduce_t<<<(BH * FEAT * NPAD + 255) / 256, 256>>>();
    gemm_out<<<dim3(SEQ / 128, BH), 256, OUT_SMEM>>>();

    gemm_bf16x3<0><<<gg, 256, GEMM_SMEM>>>(ah, al, wh + 3*WSZ, wl + 3*WSZ, bp, out, nullptr, nullptr);
}